// round 11
// baseline (speedup 1.0000x reference)
#include <cuda_runtime.h>
#include <cuda_bf16.h>

// ---------------- geometry ----------------
#define L0      512
#define P1_O    254
#define P3_O    125
#define NP3     (16*125*125) // 250000
#define N4P3    (NP3/4)      // 62500 float4
#define F6OUT   98304
#define NOUT    54
#define C5_NS   25           // 62500/25 = 2500 float4 per chunk
#define FIN_NS  12           // 24576/12 = 2048 float4 per chunk

// ---------------- task graph ----------------
#define A_TASKS 253              // c1p1 tiles of 256 px
#define B_TASKS (16*62)          // c3p3: 16 ch x 62 tiles
#define C_TASKS (15*C5_NS)       // 375 c5 blocks
#define D_TASKS 1536             // f6 tiles of 64 rows
#define E_TASKS (NOUT*FIN_NS)    // 648 fin blocks
#define A_END  A_TASKS
#define B_END  (A_END + B_TASKS)
#define C_END  (B_END + C_TASKS)
#define D_END  (C_END + D_TASKS)
#define E_END  (D_END + E_TASKS)
#define GRID   444               // 148 SMs x 3 -> fully resident, spins safe

// ---------------- scratch ----------------
__device__ __align__(16) float g_p1[6*P1_O*P1_O];
__device__ __align__(16) float g_p3[NP3];
__device__ __align__(16) float g_c5part[120*C5_NS];
__device__ __align__(16) float g_c5[120];
__device__ __align__(16) float g_f6[F6OUT];
__device__ __align__(16) float g_fpart[NOUT*FIN_NS];
__device__ int g_task;
__device__ int g_cntA;
__device__ int g_cntBc[16];
__device__ int g_c5cnt;
__device__ int g_c5flag;
__device__ int g_chunk[FIN_NS];
__device__ int g_fincnt;

__global__ void k_reset() {
    int t = threadIdx.x;
    if (t == 0) { g_task = 0; g_cntA = 0; g_c5cnt = 0; g_c5flag = 0; g_fincnt = 0; }
    if (t < 16) g_cntBc[t] = 0;
    if (t < FIN_NS) g_chunk[t] = 0;
}

__device__ __forceinline__ float dot4(float4 a, float4 b) {
    return a.x*b.x + a.y*b.y + a.z*b.z + a.w*b.w;
}

__device__ __forceinline__ void spin_ge(int* p, int v) {
    while (atomicAdd(p, 0) < v) __nanosleep(100);
}

__global__ void __launch_bounds__(256, 3)
k_mega(const float* __restrict__ x,
       const float* __restrict__ W1, const float* __restrict__ b1,
       const float* __restrict__ W3, const float* __restrict__ b3,
       const float* __restrict__ W5, const float* __restrict__ b5,
       const float* __restrict__ W6, const float* __restrict__ b6,
       const float* __restrict__ W7, const float* __restrict__ b7,
       float* __restrict__ out) {
    __shared__ __align__(16) float s_f[8*256];   // 8KB, re-used per phase
    __shared__ int sh_t, sh_last;
    const int tid = threadIdx.x;

    const unsigned MASKS[16] = {
        0x07u, 0x0Eu, 0x1Cu, 0x38u, 0x31u, 0x23u,
        0x0Fu, 0x1Eu, 0x3Cu, 0x39u, 0x33u, 0x27u,
        0x1Bu, 0x36u, 0x2Du, 0x3Fu };

    for (;;) {
        __syncthreads();                       // protect smem + sh_t reuse
        if (tid == 0) sh_t = atomicAdd(&g_task, 1);
        __syncthreads();
        const int t = sh_t;
        if (t >= E_END) return;

        if (t < A_END) {
            // ---------------- Phase A: c1p1 tile ----------------
            float* sw = s_f; float* sb = s_f + 152;
            if (tid < 150) sw[tid] = W1[tid];
            if (tid < 6)   sb[tid] = b1[tid];
            __syncthreads();
            int idx = t * 256 + tid;
            if (idx < P1_O * P1_O) {
                int py = idx / P1_O, px = idx % P1_O;
                float p[36];
#pragma unroll
                for (int i = 0; i < 6; i++)
#pragma unroll
                    for (int j = 0; j < 6; j++)
                        p[i*6+j] = x[(2*py + i)*L0 + 2*px + j];
#pragma unroll
                for (int o = 0; o < 6; o++) {
                    float b = sb[o];
                    float a00 = b, a01 = b, a10 = b, a11 = b;
#pragma unroll
                    for (int i = 0; i < 5; i++)
#pragma unroll
                        for (int j = 0; j < 5; j++) {
                            float w = sw[o*25 + i*5 + j];
                            a00 = fmaf(p[ i   *6 + j    ], w, a00);
                            a01 = fmaf(p[ i   *6 + j + 1], w, a01);
                            a10 = fmaf(p[(i+1)*6 + j    ], w, a10);
                            a11 = fmaf(p[(i+1)*6 + j + 1], w, a11);
                        }
                    g_p1[o*P1_O*P1_O + idx] = 0.25f *
                        (fmaxf(a00,0.f) + fmaxf(a01,0.f) +
                         fmaxf(a10,0.f) + fmaxf(a11,0.f));
                }
            }
            __threadfence();
            __syncthreads();
            if (tid == 0) atomicAdd(&g_cntA, 1);

        } else if (t < B_END) {
            // ---------------- Phase B: c3p3 tile ----------------
            int tb = t - A_END;
            int oc = tb / 62, xb = tb % 62;
            if (tid == 0) spin_ge(&g_cntA, A_TASKS);
            __syncthreads();
            __threadfence();
            float* sw = s_f; float* sbp = s_f + 152;
            if (tid < 150) sw[tid] = W3[oc*150 + tid];
            if (tid == 0)  sbp[0] = b3[oc];
            __syncthreads();
            unsigned mask = MASKS[oc];
            int idx = xb * 256 + tid;
            if (idx < P3_O * P3_O) {
                int py = idx / P3_O, px = idx % P3_O;
                float b = sbp[0];
                float a00 = b, a01 = b, a10 = b, a11 = b;
#pragma unroll
                for (int c = 0; c < 6; c++) {
                    if ((mask >> c) & 1u) {
                        float p[36];
                        const float* src = g_p1 + c*P1_O*P1_O + (2*py)*P1_O + 2*px;
#pragma unroll
                        for (int i = 0; i < 6; i++)
#pragma unroll
                            for (int j = 0; j < 6; j++)
                                p[i*6+j] = src[i*P1_O + j];
#pragma unroll
                        for (int i = 0; i < 5; i++)
#pragma unroll
                            for (int j = 0; j < 5; j++) {
                                float w = sw[c*25 + i*5 + j];
                                a00 = fmaf(p[ i   *6 + j    ], w, a00);
                                a01 = fmaf(p[ i   *6 + j + 1], w, a01);
                                a10 = fmaf(p[(i+1)*6 + j    ], w, a10);
                                a11 = fmaf(p[(i+1)*6 + j + 1], w, a11);
                            }
                    }
                }
                g_p3[oc*P3_O*P3_O + idx] = 0.25f *
                    (fmaxf(a00,0.f) + fmaxf(a01,0.f) +
                     fmaxf(a10,0.f) + fmaxf(a11,0.f));
            }
            __threadfence();
            __syncthreads();
            if (tid == 0) atomicAdd(&g_cntBc[oc], 1);

        } else if (t < C_END) {
            // ---------------- Phase C: c5 split-K block ----------------
            int tc = t - B_END;
            int s  = tc / 15, og = tc % 15;
            const int per = N4P3 / C5_NS;         // 2500
            int start = s * per, end = start + per;
            // channels covered by this chunk (15625 floats per channel)
            int lo = (s * 10000) / 15625;
            int hi = (s * 10000 + 9999) / 15625;
            if (tid == 0)
                for (int c = lo; c <= hi; c++) spin_ge(&g_cntBc[c], 62);
            __syncthreads();
            __threadfence();

            const float4* __restrict__ h = (const float4*)g_p3;
            const float4* w[8];
#pragma unroll
            for (int r = 0; r < 8; r++)
                w[r] = (const float4*)(W5 + (size_t)(8*og + r) * NP3);
            float acc[8];
#pragma unroll
            for (int r = 0; r < 8; r++) acc[r] = 0.f;
#pragma unroll 2
            for (int i = start + tid; i < end; i += 256) {
                float4 hv = h[i];
                float4 xv[8];
#pragma unroll
                for (int r = 0; r < 8; r++) xv[r] = __ldcs(&w[r][i]);
#pragma unroll
                for (int r = 0; r < 8; r++) acc[r] += dot4(xv[r], hv);
            }
#pragma unroll
            for (int r = 0; r < 8; r++) s_f[r*256 + tid] = acc[r];
            __syncthreads();
            {
                int r = tid >> 5, c = tid & 31;
                float v = 0.f;
#pragma unroll
                for (int k = 0; k < 8; k++) v += s_f[r*256 + c + 32*k];
#pragma unroll
                for (int off = 16; off > 0; off >>= 1)
                    v += __shfl_down_sync(0xFFFFFFFFu, v, off);
                if (c == 0) g_c5part[(8*og + r) * C5_NS + s] = v;
            }
            __threadfence();
            __syncthreads();
            if (tid == 0) {
                int tt = atomicAdd(&g_c5cnt, 1);
                sh_last = (tt == C_TASKS - 1);
            }
            __syncthreads();
            if (sh_last) {
                if (tid < 120) {
                    float a = b5[tid];
#pragma unroll
                    for (int ss = 0; ss < C5_NS; ss++) a += g_c5part[tid*C5_NS + ss];
                    g_c5[tid] = fmaxf(a, 0.0f);
                }
                __threadfence();
                __syncthreads();
                if (tid == 0) atomicAdd(&g_c5flag, 1);
            }

        } else if (t < D_END) {
            // ---------------- Phase D: f6 tile (64 rows) ----------------
            int td = t - C_END;
            if (tid == 0) spin_ge(&g_c5flag, 1);
            __syncthreads();
            __threadfence();
            if (tid < 120) s_f[tid] = g_c5[tid];
            __syncthreads();

            int warp = tid >> 5, lane = tid & 31, quad = lane & 3;
            int row  = td * 64 + warp * 8 + (lane >> 2);
            const float4* __restrict__ w  = (const float4*)(W6 + (size_t)row * 120);
            const float4* __restrict__ s4 = (const float4*)s_f;
            float acc0 = 0.f, acc1 = 0.f;
#pragma unroll
            for (int it = 0; it < 8; it++) {
                int k = quad + it * 4;
                if (k < 30) {
                    float4 a = __ldg(&w[k]);
                    float4 b = s4[k];
                    float d = dot4(a, b);
                    if (it & 1) acc1 += d; else acc0 += d;
                }
            }
            float acc = acc0 + acc1;
            acc += __shfl_xor_sync(0xFFFFFFFFu, acc, 1);
            acc += __shfl_xor_sync(0xFFFFFFFFu, acc, 2);
            if (quad == 0)
                g_f6[row] = fmaxf(acc + __ldg(&b6[row]), 0.0f);
            __threadfence();
            __syncthreads();
            if (tid == 0) atomicAdd(&g_chunk[td >> 7], 1);

        } else {
            // ---------------- Phase E: fin split-K block ----------------
            int te = t - D_END;
            int s  = te / NOUT, o = te % NOUT;
            if (tid == 0) spin_ge(&g_chunk[s], 128);
            __syncthreads();
            __threadfence();

            const float4* __restrict__ w = (const float4*)(W7 + (size_t)o * F6OUT);
            const float4* __restrict__ h = (const float4*)g_f6;
            const int per = (F6OUT/4) / FIN_NS;   // 2048
            int base = s * per + tid;
            float acc0 = 0.f, acc1 = 0.f;
#pragma unroll
            for (int it = 0; it < 8; it++) {
                int i = base + it * 256;
                float4 a = __ldcs(&w[i]);
                float4 b = h[i];
                float d = dot4(a, b);
                if (it & 1) acc1 += d; else acc0 += d;
            }
            float acc = acc0 + acc1;
            s_f[tid] = acc;
            __syncthreads();
#pragma unroll
            for (int st = 128; st > 0; st >>= 1) {
                if (tid < st) s_f[tid] += s_f[tid + st];
                __syncthreads();
            }
            if (tid == 0) g_fpart[o * FIN_NS + s] = s_f[0];
            __threadfence();
            __syncthreads();
            if (tid == 0) {
                int tt = atomicAdd(&g_fincnt, 1);
                sh_last = (tt == E_TASKS - 1);
            }
            __syncthreads();
            if (sh_last) {
                if (tid < NOUT) {
                    float a = b7[tid];
#pragma unroll
                    for (int ss = 0; ss < FIN_NS; ss++) a += g_fpart[tid*FIN_NS + ss];
                    out[tid] = a;
                }
            }
        }
    }
}

// ---------------- launch ----------------
extern "C" void kernel_launch(void* const* d_in, const int* in_sizes, int n_in,
                              void* d_out, int out_size) {
    const float* x  = (const float*)d_in[0];
    const float* W1 = (const float*)d_in[1];
    const float* b1 = (const float*)d_in[2];
    const float* W3 = (const float*)d_in[3];
    const float* b3 = (const float*)d_in[4];
    const float* W5 = (const float*)d_in[5];
    const float* b5 = (const float*)d_in[6];
    const float* W6 = (const float*)d_in[7];
    const float* b6 = (const float*)d_in[8];
    const float* W7 = (const float*)d_in[9];
    const float* b7 = (const float*)d_in[10];
    float* out = (float*)d_out;

    k_reset<<<1, 32>>>();
    k_mega<<<GRID, 256>>>(x, W1, b1, W3, b3, W5, b5, W6, b6, W7, b7, out);
}

// round 12
// speedup vs baseline: 1.1762x; 1.1762x over previous
#include <cuda_runtime.h>
#include <cuda_bf16.h>

// ---------------- geometry ----------------
#define L0      512
#define P1_O    254
#define P3_O    125
#define NP3     (16*125*125) // 250000
#define N4P3    (NP3/4)      // 62500 float4
#define F6OUT   98304
#define NOUT    54
#define C5_NS   25           // 62500/25 = 2500 exact
#define FIN_NS  12           // 24576/12 = 2048 exact
#define F6_BLKS 1536         // 64 rows each
#define FIN_TASKS (NOUT*FIN_NS)     // 648
#define FIN_START (F6_BLKS - FIN_TASKS)   // 888

// ---------------- scratch ----------------
__device__ __align__(16) float g_p1[6*P1_O*P1_O];
__device__ __align__(16) float g_p3[NP3];
__device__ __align__(16) float g_c5part[120*C5_NS];
__device__ __align__(16) float g_c5[120];
__device__ __align__(16) float g_f6[F6OUT];
__device__ __align__(16) float g_fpart[NOUT*FIN_NS];
__device__ int g_c5cnt;
__device__ int g_fincnt;
__device__ int g_chunk[FIN_NS];      // zero-init; self-resetting via ack
__device__ int g_chunkack[FIN_NS];   // zero-init; self-resetting

__device__ __forceinline__ float dot4(float4 a, float4 b) {
    return a.x*b.x + a.y*b.y + a.z*b.z + a.w*b.w;
}

// ---------------- fused C1 conv 5x5 + ReLU + 2x2 avgpool ----------------
__global__ void k_c1p1(const float* __restrict__ x,
                       const float* __restrict__ W1,
                       const float* __restrict__ b1) {
    __shared__ float sw[6*25];
    __shared__ float sb[6];
    if (threadIdx.x < 150) sw[threadIdx.x] = W1[threadIdx.x];
    if (threadIdx.x < 6)   sb[threadIdx.x] = b1[threadIdx.x];
    __syncthreads();

    int idx = blockIdx.x * blockDim.x + threadIdx.x;
    if (idx >= P1_O * P1_O) return;
    int py = idx / P1_O, px = idx % P1_O;

    float p[36];
#pragma unroll
    for (int i = 0; i < 6; i++)
#pragma unroll
        for (int j = 0; j < 6; j++)
            p[i*6+j] = x[(2*py + i)*L0 + 2*px + j];

#pragma unroll
    for (int o = 0; o < 6; o++) {
        float b = sb[o];
        float a00 = b, a01 = b, a10 = b, a11 = b;
#pragma unroll
        for (int i = 0; i < 5; i++)
#pragma unroll
            for (int j = 0; j < 5; j++) {
                float w = sw[o*25 + i*5 + j];
                a00 = fmaf(p[ i   *6 + j    ], w, a00);
                a01 = fmaf(p[ i   *6 + j + 1], w, a01);
                a10 = fmaf(p[(i+1)*6 + j    ], w, a10);
                a11 = fmaf(p[(i+1)*6 + j + 1], w, a11);
            }
        g_p1[o*P1_O*P1_O + idx] = 0.25f * (fmaxf(a00,0.f) + fmaxf(a01,0.f) +
                                           fmaxf(a10,0.f) + fmaxf(a11,0.f));
    }
}

// ---------------- fused C3 sparse conv 5x5 + ReLU + 2x2 avgpool ----------------
__global__ void k_c3p3(const float* __restrict__ W3,
                       const float* __restrict__ b3) {
    int oc = blockIdx.y;
    __shared__ float sw[6*25];
    __shared__ float sb;
    if (threadIdx.x < 150) sw[threadIdx.x] = W3[oc*150 + threadIdx.x];
    if (threadIdx.x == 0)  sb = b3[oc];
    __syncthreads();

    const unsigned MASKS[16] = {
        0x07u, 0x0Eu, 0x1Cu, 0x38u, 0x31u, 0x23u,
        0x0Fu, 0x1Eu, 0x3Cu, 0x39u, 0x33u, 0x27u,
        0x1Bu, 0x36u, 0x2Du, 0x3Fu };
    unsigned mask = MASKS[oc];

    int idx = blockIdx.x * blockDim.x + threadIdx.x;
    if (idx >= P3_O * P3_O) return;
    int py = idx / P3_O, px = idx % P3_O;

    float b = sb;
    float a00 = b, a01 = b, a10 = b, a11 = b;

#pragma unroll
    for (int c = 0; c < 6; c++) {
        if ((mask >> c) & 1u) {
            float p[36];
            const float* src = g_p1 + c*P1_O*P1_O + (2*py)*P1_O + 2*px;
#pragma unroll
            for (int i = 0; i < 6; i++)
#pragma unroll
                for (int j = 0; j < 6; j++)
                    p[i*6+j] = src[i*P1_O + j];
#pragma unroll
            for (int i = 0; i < 5; i++)
#pragma unroll
                for (int j = 0; j < 5; j++) {
                    float w = sw[c*25 + i*5 + j];
                    a00 = fmaf(p[ i   *6 + j    ], w, a00);
                    a01 = fmaf(p[ i   *6 + j + 1], w, a01);
                    a10 = fmaf(p[(i+1)*6 + j    ], w, a10);
                    a11 = fmaf(p[(i+1)*6 + j + 1], w, a11);
                }
        }
    }
    g_p3[oc*P3_O*P3_O + idx] = 0.25f * (fmaxf(a00,0.f) + fmaxf(a01,0.f) +
                                        fmaxf(a10,0.f) + fmaxf(a11,0.f));
}

// ---------------- C5: 8 outputs/block, split-K, last-block reduce ----------------
__global__ void __launch_bounds__(256, 3) k_c5(const float* __restrict__ W5,
                                               const float* __restrict__ b5) {
    int og = blockIdx.x;          // 0..14
    int s  = blockIdx.y;          // 0..C5_NS-1
    const int per = N4P3 / C5_NS; // 2500
    int start = s * per, end = start + per;

    const float4* __restrict__ h = (const float4*)g_p3;
    const float4* w[8];
#pragma unroll
    for (int r = 0; r < 8; r++)
        w[r] = (const float4*)(W5 + (size_t)(8*og + r) * NP3);

    float acc[8];
#pragma unroll
    for (int r = 0; r < 8; r++) acc[r] = 0.f;

#pragma unroll 2
    for (int i = start + threadIdx.x; i < end; i += 256) {
        float4 hv = h[i];
        float4 xv[8];
#pragma unroll
        for (int r = 0; r < 8; r++) xv[r] = __ldcs(&w[r][i]);
#pragma unroll
        for (int r = 0; r < 8; r++) acc[r] += dot4(xv[r], hv);
    }

    __shared__ float red[8*256];
#pragma unroll
    for (int r = 0; r < 8; r++) red[r*256 + threadIdx.x] = acc[r];
    __syncthreads();
    {
        int r = threadIdx.x >> 5;
        int c = threadIdx.x & 31;
        float v = 0.f;
#pragma unroll
        for (int k = 0; k < 8; k++) v += red[r*256 + c + 32*k];
#pragma unroll
        for (int off = 16; off > 0; off >>= 1)
            v += __shfl_down_sync(0xFFFFFFFFu, v, off);
        if (c == 0) g_c5part[(8*og + r) * C5_NS + s] = v;
    }

    __shared__ int slast;
    __syncthreads();
    if (threadIdx.x == 0) {
        __threadfence();
        int t = atomicAdd(&g_c5cnt, 1);
        slast = (t == 15*C5_NS - 1);
    }
    __syncthreads();
    if (slast) {
        int oo = threadIdx.x;
        if (oo < 120) {
            float a = b5[oo];
#pragma unroll
            for (int ss = 0; ss < C5_NS; ss++) a += g_c5part[oo*C5_NS + ss];
            g_c5[oo] = fmaxf(a, 0.0f);
        }
        if (threadIdx.x == 0) g_c5cnt = 0;
    }
}

// ---------------- fused F6 + FIN ----------------
// All 1536 blocks: round-5 f6 body (64 rows) -> publish chunk (bid>>7).
// Blocks >= 888 then run one fin task; mapping s = fb/54 puts late chunks on
// the latest blocks, so waits are ~zero and no residency is wasted spinning.
__global__ void __launch_bounds__(256, 5)
k_f6fin(const float* __restrict__ W6, const float* __restrict__ b6,
        const float* __restrict__ W7, const float* __restrict__ b7,
        float* __restrict__ out) {
    __shared__ __align__(16) float sh[256];
    const int bid = blockIdx.x;
    const int tid = threadIdx.x;

    // ---------- F6 part ----------
    if (tid < 120) sh[tid] = g_c5[tid];
    __syncthreads();
    {
        int warp = tid >> 5;
        int lane = tid & 31;
        int quad = lane & 3;
        int row  = bid * 64 + warp * 8 + (lane >> 2);
        const float4* __restrict__ w  = (const float4*)(W6 + (size_t)row * 120);
        const float4* __restrict__ s4 = (const float4*)sh;

        float acc0 = 0.f, acc1 = 0.f;
#pragma unroll
        for (int it = 0; it < 8; it++) {
            int k = quad + it * 4;
            if (k < 30) {
                float4 a = __ldg(&w[k]);
                float4 b = s4[k];
                float d = dot4(a, b);
                if (it & 1) acc1 += d; else acc0 += d;
            }
        }
        float acc = acc0 + acc1;
        acc += __shfl_xor_sync(0xFFFFFFFFu, acc, 1);
        acc += __shfl_xor_sync(0xFFFFFFFFu, acc, 2);
        if (quad == 0)
            g_f6[row] = fmaxf(acc + __ldg(&b6[row]), 0.0f);
    }
    __threadfence();
    __syncthreads();
    if (tid == 0) atomicAdd(&g_chunk[bid >> 7], 1);

    if (bid < FIN_START) return;

    // ---------- FIN part ----------
    int fb = bid - FIN_START;     // 0..647
    int s  = fb / NOUT;           // chunk 0..11 (late chunks on late blocks)
    int o  = fb % NOUT;

    if (tid == 0) {
        while (atomicAdd(&g_chunk[s], 0) < 128)
            __nanosleep(100);
    }
    __syncthreads();
    __threadfence();              // acquire g_f6 chunk

    const float4* __restrict__ w = (const float4*)(W7 + (size_t)o * F6OUT);
    const float4* __restrict__ h = (const float4*)g_f6;
    const int per = (F6OUT/4) / FIN_NS;    // 2048
    int base = s * per + tid;

    float acc0 = 0.f, acc1 = 0.f;
#pragma unroll
    for (int it = 0; it < 8; it++) {
        int i = base + it * 256;
        float4 a = __ldcs(&w[i]);
        float4 b = h[i];
        float d = dot4(a, b);
        if (it & 1) acc1 += d; else acc0 += d;
    }
    float acc = acc0 + acc1;

    sh[tid] = acc;
    __syncthreads();
#pragma unroll
    for (int st = 128; st > 0; st >>= 1) {
        if (tid < st) sh[tid] += sh[tid + st];
        __syncthreads();
    }
    __shared__ int slast;
    if (tid == 0) {
        g_fpart[o * FIN_NS + s] = sh[0];
        __threadfence();
        int t = atomicAdd(&g_fincnt, 1);
        slast = (t == FIN_TASKS - 1);
        int a = atomicAdd(&g_chunkack[s], 1);
        if (a == NOUT - 1) { g_chunk[s] = 0; g_chunkack[s] = 0; }  // replay reset
    }
    __syncthreads();
    if (slast) {
        int oo = tid;
        if (oo < NOUT) {
            float a = b7[oo];
#pragma unroll
            for (int ss = 0; ss < FIN_NS; ss++) a += g_fpart[oo*FIN_NS + ss];
            out[oo] = a;
        }
        if (tid == 0) g_fincnt = 0;
    }
}

// ---------------- launch ----------------
extern "C" void kernel_launch(void* const* d_in, const int* in_sizes, int n_in,
                              void* d_out, int out_size) {
    const float* x  = (const float*)d_in[0];
    const float* W1 = (const float*)d_in[1];
    const float* b1 = (const float*)d_in[2];
    const float* W3 = (const float*)d_in[3];
    const float* b3 = (const float*)d_in[4];
    const float* W5 = (const float*)d_in[5];
    const float* b5 = (const float*)d_in[6];
    const float* W6 = (const float*)d_in[7];
    const float* b6 = (const float*)d_in[8];
    const float* W7 = (const float*)d_in[9];
    const float* b7 = (const float*)d_in[10];
    float* out = (float*)d_out;

    k_c1p1<<<(P1_O*P1_O + 255)/256, 256>>>(x, W1, b1);
    k_c3p3<<<dim3((P3_O*P3_O + 255)/256, 16), 256>>>(W3, b3);
    k_c5<<<dim3(15, C5_NS), 256>>>(W5, b5);
    k_f6fin<<<F6_BLKS, 256>>>(W6, b6, W7, b7, out);
}